// round 15
// baseline (speedup 1.0000x reference)
#include <cuda_runtime.h>
#include <math.h>

// ---------------------------------------------------------------------------
// QConv2D: 4-qubit circuit on every 2x2 patch of x(32,1,128,128).
// Z_w(patch) = P_L^T B_w P_R,  P = g_top (x) g_bot, g=(1,cos x,sin x).
// B_w (4 x 9 x 9) from params via tiny precompute kernel (PDL-overlapped).
// Main kernel: Horner-factored bilinear form, packed f32x2 FMA, 8 patches
// per thread as 4 packed chains -> 4 consecutive FMA2 share each coefficient
// register (operand-reuse cache mitigates FFMA2 RF-bank rt=3).
// ---------------------------------------------------------------------------

typedef unsigned long long u64;

#define FMA2(acc, a, b) \
    asm("fma.rn.f32x2 %0, %1, %2, %0;" : "+l"(acc) : "l"(a), "l"(b))
#define FMA2N(d, a, b, c) \
    asm("fma.rn.f32x2 %0, %1, %2, %3;" : "=l"(d) : "l"(a), "l"(b), "l"(c))

__device__ __forceinline__ u64 pk(float lo, float hi) {
    u64 r; asm("mov.b64 %0, {%1, %2};" : "=l"(r) : "f"(lo), "f"(hi)); return r;
}
__device__ __forceinline__ void upk(float& lo, float& hi, u64 v) {
    asm("mov.b64 {%0, %1}, %2;" : "=f"(lo), "=f"(hi) : "l"(v));
}
__device__ __forceinline__ float2 cmulf(float2 a, float2 b) {
    return make_float2(a.x * b.x - a.y * b.y, a.x * b.y + a.y * b.x);
}

// B coefficients, duplicated {c,c}; row (w,a) = 10 u64 slots (80B):
// slots 0..8 = B_w[a][b] (b = 3*k1+k3), slot 9 = pad.
__device__ u64 d_Bg[4 * 9 * 10];

// ---------------------------- precompute kernel ----------------------------
__global__ void qconv_precompute(const float* __restrict__ params) {
    __shared__ float2 shM[2][4][2][2];
    __shared__ float2 shG[2][16][16];
    __shared__ float2 shU[16][16];
    __shared__ float  shA[4][16][16];
    const int tid = threadIdx.x;

    if (tid < 8) {  // single-qubit mats m = RZ(tz)*RX(tx)
        int l = tid >> 2, w = tid & 3;
        float tx = params[(l * 4 + w) * 2 + 0];
        float tz = params[(l * 4 + w) * 2 + 1];
        float s, c, sz, cz;
        sincosf(0.5f * tx, &s, &c);
        sincosf(0.5f * tz, &sz, &cz);
        shM[l][w][0][0] = make_float2(cz * c, -sz * c);
        shM[l][w][0][1] = make_float2(-s * sz, -s * cz);
        shM[l][w][1][0] = make_float2(s * sz, -s * cz);
        shM[l][w][1][1] = make_float2(c * cz, c * sz);
    }
    __syncthreads();

    {   // G_l = CNOTperm * (m0 (x) m1 (x) m2 (x) m3)
        int i = tid >> 4, j = tid & 15;
        int r = i;
        if (r & 1) r ^= 2;
        if (r & 2) r ^= 4;
        if (r & 4) r ^= 8;
#pragma unroll
        for (int l = 0; l < 2; l++) {
            float2 g = shM[l][0][(r >> 3) & 1][(j >> 3) & 1];
            g = cmulf(g, shM[l][1][(r >> 2) & 1][(j >> 2) & 1]);
            g = cmulf(g, shM[l][2][(r >> 1) & 1][(j >> 1) & 1]);
            g = cmulf(g, shM[l][3][r & 1][j & 1]);
            shG[l][i][j] = g;
        }
    }
    __syncthreads();

    {   // U = G1 * G0
        int i = tid >> 4, j = tid & 15;
        float2 acc = make_float2(0.f, 0.f);
#pragma unroll
        for (int m = 0; m < 16; m++) {
            float2 a = shG[1][i][m], bb = shG[0][m][j];
            acc.x += a.x * bb.x - a.y * bb.y;
            acc.y += a.x * bb.y + a.y * bb.x;
        }
        shU[i][j] = acc;
    }
    __syncthreads();

    {   // A_w[i][j] = Re( i^{popc(i)-popc(j)} sum_k d_w(k) conj(U[k,i]) U[k,j] )
        int i = tid >> 4, j = tid & 15;
        float ar[4] = {0, 0, 0, 0}, ai[4] = {0, 0, 0, 0};
#pragma unroll
        for (int k = 0; k < 16; k++) {
            float2 ui = shU[k][i], uj = shU[k][j];
            float cr = ui.x * uj.x + ui.y * uj.y;
            float ci = ui.x * uj.y - ui.y * uj.x;
#pragma unroll
            for (int w = 0; w < 4; w++) {
                float sgn = (k & (1 << (3 - w))) ? -1.f : 1.f;
                ar[w] += sgn * cr;
                ai[w] += sgn * ci;
            }
        }
        int ph = (__popc(i) - __popc(j)) & 3;
#pragma unroll
        for (int w = 0; w < 4; w++) {
            float re;
            if (ph == 0)      re =  ar[w];
            else if (ph == 1) re = -ai[w];
            else if (ph == 2) re = -ar[w];
            else              re =  ai[w];
            shA[w][i][j] = re;
        }
    }
    __syncthreads();

    // half-angle -> full-angle basis, write duplicated {v,v}
    for (int idx = tid; idx < 324; idx += 256) {
        int w = idx / 81, r = idx % 81;
        int a = r / 9, bq = r % 9;
        int k0 = a / 3, k2 = a % 3, k1 = bq / 3, k3 = bq % 3;
        int xmask = ((k0 == 2) ? 8 : 0) | ((k1 == 2) ? 4 : 0) |
                    ((k2 == 2) ? 2 : 0) | ((k3 == 2) ? 1 : 0);
        int smask = ((k0 == 1) ? 8 : 0) | ((k1 == 1) ? 4 : 0) |
                    ((k2 == 1) ? 2 : 0) | ((k3 == 1) ? 1 : 0);
        float sum = 0.f;
#pragma unroll
        for (int i = 0; i < 16; i++) {
            float sgn = (__popc(i & smask) & 1) ? -1.f : 1.f;
            sum += sgn * shA[w][i][i ^ xmask];
        }
        float v = sum * (1.f / 16.f);
        unsigned ub = __float_as_uint(v);
        d_Bg[(w * 9 + a) * 10 + bq] = ((u64)ub << 32) | ub;
    }
    asm volatile("griddepcontrol.launch_dependents;" ::: "memory");
}

// ------------------------------- main kernel -------------------------------
// Block: 128 threads = 8 rows x 16 col-groups (8 patches each).
// Grid: (16 row-groups, 32 batches) = 512 blocks; 4 CTAs/SM -> one wave.
__global__ __launch_bounds__(128, 4) void qconv_main(
    const float* __restrict__ x, float* __restrict__ out)
{
    __shared__ __align__(16) u64 sBd[4 * 9 * 10];
    const int tid = threadIdx.x;

    const int b  = blockIdx.y;
    const int ti = tid >> 4;               // 0..7
    const int tj = tid & 15;               // 0..15
    const int i  = blockIdx.x * 8 + ti;    // output row (127 invalid)
    const int j0 = tj * 8;
    const int i0 = (i < 126) ? i : 126;

    const float* px = x + b * 16384 + i0 * 128 + j0;

    // ---- preamble (overlaps precompute via PDL) ----
    float tv[9], bv[9];
    {
        float4 a0 = *(const float4*)px;
        float4 a1 = *(const float4*)(px + 4);
        float4 b0 = *(const float4*)(px + 128);
        float4 b1 = *(const float4*)(px + 132);
        tv[0]=a0.x; tv[1]=a0.y; tv[2]=a0.z; tv[3]=a0.w;
        tv[4]=a1.x; tv[5]=a1.y; tv[6]=a1.z; tv[7]=a1.w;
        bv[0]=b0.x; bv[1]=b0.y; bv[2]=b0.z; bv[3]=b0.w;
        bv[4]=b1.x; bv[5]=b1.y; bv[6]=b1.z; bv[7]=b1.w;
        int e = (j0 + 8 <= 127) ? 8 : 7;
        tv[8] = px[e];
        bv[8] = px[128 + e];
    }
    float ct[9], st[9], cb[9], sb[9];
#pragma unroll
    for (int c = 0; c < 9; c++) {
        __sincosf(tv[c], &st[c], &ct[c]);
        __sincosf(bv[c], &sb[c], &cb[c]);
    }

    // Packed trig pairs {col c, col c+4}, c = 0..4.
    // Chain p (p=0..3) = patches (j0+p, j0+p+4): left pair p, right pair p+1.
    u64 CB[5], SB[5], CT[5], ST[5];
#pragma unroll
    for (int q = 0; q < 5; q++) {
        CB[q] = pk(cb[q], cb[q + 4]);
        SB[q] = pk(sb[q], sb[q + 4]);
        CT[q] = pk(ct[q], ct[q + 4]);
        ST[q] = pk(st[q], st[q + 4]);
    }

    // ---- wait for precompute, stage coefficients ----
    asm volatile("griddepcontrol.wait;" ::: "memory");
    for (int idx = tid; idx < 360; idx += 128) sBd[idx] = d_Bg[idx];
    __syncthreads();

    const bool rowok = (i < 127);
    const bool last = (j0 + 7 >= 127);     // only patch j0+7 can be invalid
    float* ob = out + ((size_t)(b * 4) * 127 + i) * 127 + j0;

#pragma unroll 1
    for (int w = 0; w < 4; w++) {
        const u64* wp = sBd + w * 90;
        u64 sA[4][3];
#pragma unroll
        for (int r = 0; r < 9; r++) {
            const int k0 = r / 3, k2 = r % 3;
            const u64* rp = wp + r * 10;
            u64 cf[10];
            *(ulonglong2*)(cf + 0) = *(const ulonglong2*)(rp + 0);
            *(ulonglong2*)(cf + 2) = *(const ulonglong2*)(rp + 2);
            *(ulonglong2*)(cf + 4) = *(const ulonglong2*)(rp + 4);
            *(ulonglong2*)(cf + 6) = *(const ulonglong2*)(rp + 6);
            *(ulonglong2*)(cf + 8) = *(const ulonglong2*)(rp + 8);

            // 4 chains interleaved: consecutive FMA2s share the coefficient
            // register (operand-reuse cache) and are independent (ILP=4).
            u64 t0[4], t1[4];
#pragma unroll
            for (int p = 0; p < 4; p++) FMA2N(t0[p], cf[1], CB[p + 1], cf[0]);
#pragma unroll
            for (int p = 0; p < 4; p++) FMA2(t0[p], cf[2], SB[p + 1]);
#pragma unroll
            for (int p = 0; p < 4; p++) FMA2N(t1[p], cf[4], CB[p + 1], cf[3]);
#pragma unroll
            for (int p = 0; p < 4; p++) FMA2(t1[p], cf[5], SB[p + 1]);
#pragma unroll
            for (int p = 0; p < 4; p++) FMA2(t0[p], CT[p + 1], t1[p]);
#pragma unroll
            for (int p = 0; p < 4; p++) FMA2N(t1[p], cf[7], CB[p + 1], cf[6]);
#pragma unroll
            for (int p = 0; p < 4; p++) FMA2(t1[p], cf[8], SB[p + 1]);
#pragma unroll
            for (int p = 0; p < 4; p++) FMA2(t0[p], ST[p + 1], t1[p]);

            if (k2 == 0) {
#pragma unroll
                for (int p = 0; p < 4; p++) sA[p][k0] = t0[p];
            } else if (k2 == 1) {
#pragma unroll
                for (int p = 0; p < 4; p++) FMA2(sA[p][k0], CB[p], t0[p]);
            } else {
#pragma unroll
                for (int p = 0; p < 4; p++) FMA2(sA[p][k0], SB[p], t0[p]);
            }
        }

        if (rowok) {
            float* orow = ob + (size_t)w * (127 * 127);
#pragma unroll
            for (int p = 0; p < 4; p++) {
                u64 z = sA[p][0];
                FMA2(z, CT[p], sA[p][1]);
                FMA2(z, ST[p], sA[p][2]);
                float lo, hi;
                upk(lo, hi, z);
                orow[p] = lo;                       // patch j0+p
                if (!last || p < 3) orow[p + 4] = hi;  // patch j0+p+4
            }
        }
    }
}

// ------------------------------- launcher ----------------------------------
extern "C" void kernel_launch(void* const* d_in, const int* in_sizes, int n_in,
                              void* d_out, int out_size) {
    const float* x      = (const float*)d_in[0];
    const float* params = (const float*)d_in[1];
    if (n_in >= 2 && in_sizes[0] == 16) {  // robustness to input order
        params = (const float*)d_in[0];
        x      = (const float*)d_in[1];
    }
    float* out = (float*)d_out;

    qconv_precompute<<<1, 256>>>(params);

    dim3 grid(16, 32);   // 16 row-groups (8 rows) x 32 batches = 512 blocks
    cudaLaunchConfig_t cfg = {};
    cfg.gridDim = grid;
    cfg.blockDim = dim3(128, 1, 1);
    cfg.dynamicSmemBytes = 0;
    cfg.stream = 0;
    cudaLaunchAttribute attr[1];
    attr[0].id = cudaLaunchAttributeProgrammaticStreamSerialization;
    attr[0].val.programmaticStreamSerializationAllowed = 1;
    cfg.attrs = attr;
    cfg.numAttrs = 1;
    cudaError_t err = cudaLaunchKernelEx(&cfg, qconv_main, x, out);
    if (err != cudaSuccess) {
        qconv_main<<<grid, 128>>>(x, out);   // fallback, still correct
    }
}